// round 7
// baseline (speedup 1.0000x reference)
#include <cuda_runtime.h>

constexpr int HH = 512;
constexpr int WW = 512;
constexpr int NB = 9;
constexpr int OH = 32;
constexpr int OW = 32;
constexpr int BMAX = 8;

#define PIF 3.14159265358979323846f

// ---------------- scratch ----------------
__device__ float2 g_vab[BMAX * HH * WW];           // (wa*I, wb*I) per pixel
__device__ unsigned char g_k0[BMAX * HH * WW];     // base bin in [0,7]
__device__ float g_hog [BMAX * NB * OH * OW];
__device__ float g_maxn[BMAX];                     // atomicMax accumulator (>=0)
__device__ float g_q   [BMAX * 2 * OH * OW];
__device__ float g_wt  [WW * 6];
__device__ int   g_ws  [WW];

// ---------------- fused grayscale + gradient + bin decomposition ----------------
__global__ void grad_kernel(const float* __restrict__ x) {
    __shared__ float sg[10][34];
    int b = blockIdx.z;
    int x0 = blockIdx.x * 32, y0 = blockIdx.y * 8;
    const float* xb = x + (size_t)b * 3 * HH * WW;
    int tid = threadIdx.y * 32 + threadIdx.x;

    if (tid == 0) g_maxn[b] = 0.0f;   // reset for hog's atomicMax (all blocks write 0)

    for (int i = tid; i < 10 * 34; i += 256) {
        int ly = i / 34, lx = i - ly * 34;
        int gy = y0 + ly - 1, gx = x0 + lx - 1;
        float v = 0.0f;
        if (gy >= 0 && gy < HH && gx >= 0 && gx < WW) {
            int p = gy * WW + gx;
            v = 0.299f * xb[p] + 0.587f * xb[p + HH * WW] + 0.114f * xb[p + 2 * HH * WW];
        }
        sg[ly][lx] = v;
    }
    __syncthreads();

    int lx = threadIdx.x, ly = threadIdx.y;
    float gx = sg[ly + 1][lx + 2] - sg[ly + 1][lx];
    float gy = sg[ly + 2][lx + 1] - sg[ly][lx + 1];
    float inten = sqrtf(gx * gx + gy * gy);
    float a = atan2f(gy, gx) + PIF;      // >= 0
    float r = fmodf(a, PIF);             // jnp.mod (positive arg) == fmod
    float o = r / PIF * 180.0f;          // [0,180)

    int k0 = (int)floorf((o - 10.0f) * 0.05f);   // [-1,8]
    float c0 = 10.0f + 20.0f * (float)k0;
    float wa = fminf(fmaxf(1.0f - (fabsf(o - c0) * 9.0f) / 180.0f, 0.0f), 1.0f);
    float wb = fminf(fmaxf(1.0f - (fabsf(o - (c0 + 20.0f)) * 9.0f) / 180.0f, 0.0f), 1.0f);
    float va = wa * inten, vb = wb * inten;
    if (k0 < 0)      { k0 = 0; va = vb; vb = 0.0f; }
    else if (k0 > 7) { k0 = 7; vb = va; va = 0.0f; }

    int p = b * HH * WW + (y0 + ly) * WW + (x0 + lx);
    g_vab[p] = make_float2(va, vb);
    g_k0[p] = (unsigned char)k0;
}

__device__ __forceinline__ int refl(int m) {
    m = (m < 0) ? -m : m;
    m = (m > HH - 1) ? (2 * (HH - 1) - m) : m;
    return m;
}

// ---------------- HOG aggregation + fused per-cell norm -> atomicMax ----------------
__global__ void hog_kernel() {
    __shared__ float sacc[NB][256];     // bank(tid) independent of bin -> conflict-free
    __shared__ int srow[33], scol[33];
    __shared__ float sbin[NB];
    int b = blockIdx.y;
    int cell = blockIdx.x;
    int oy = cell >> 5, ox = cell & 31;
    int tid = threadIdx.x;

    if (tid < 33) {
        srow[tid] = refl(oy * 16 - 16 + tid) * WW;
        scol[tid] = refl(ox * 16 - 16 + tid);
    }
#pragma unroll
    for (int k = 0; k < NB; k++) sacc[k][tid] = 0.0f;
    __syncthreads();

    const float2* __restrict__ V = g_vab + b * HH * WW;
    const unsigned char* __restrict__ K = g_k0 + b * HH * WW;

    // 1089 taps: 4 per thread + tail of 65
    float2 v[4]; float f[4]; int kk[4];
#pragma unroll
    for (int j = 0; j < 4; j++) {
        int t = tid + j * 256;
        int dy = t / 33;
        int dx = t - dy * 33;
        int gi = srow[dy] + scol[dx];
        v[j] = __ldg(&V[gi]);
        kk[j] = (int)K[gi];
        float fy = (float)(dy - 16), fx = (float)(dx - 16);
        f[j] = 1.0f - sqrtf(fy * fy + fx * fx) / 22.627417f;
    }
#pragma unroll
    for (int j = 0; j < 4; j++) {
        sacc[kk[j]][tid]     += f[j] * v[j].x;
        sacc[kk[j] + 1][tid] += f[j] * v[j].y;
    }
    if (tid < 65) {
        int t = 1024 + tid;
        int dy = t / 33;
        int dx = t - dy * 33;
        int gi = srow[dy] + scol[dx];
        float2 vt = __ldg(&V[gi]);
        int kt = (int)K[gi];
        float fy = (float)(dy - 16), fx = (float)(dx - 16);
        float ft = 1.0f - sqrtf(fy * fy + fx * fx) / 22.627417f;
        sacc[kt][tid]     += ft * vt.x;
        sacc[kt + 1][tid] += ft * vt.y;
    }
    __syncthreads();

    // warp w reduces bins k = w, w+8 (strided LDS + shuffle tree)
    int w = tid >> 5, l = tid & 31;
    for (int k = w; k < NB; k += 8) {
        float s = 0.0f;
#pragma unroll
        for (int i = 0; i < 8; i++) s += sacc[k][l + 32 * i];
#pragma unroll
        for (int off = 16; off > 0; off >>= 1)
            s += __shfl_down_sync(0xffffffffu, s, off);
        if (l == 0) {
            g_hog[(b * NB + k) * (OH * OW) + cell] = s;
            sbin[k] = s;
        }
    }
    __syncthreads();

    // cell L2 norm over bins -> per-batch max (atomic on int view; all values >= 0)
    if (tid == 0) {
        float s2 = 0.0f;
#pragma unroll
        for (int k = 0; k < NB; k++) s2 += sbin[k] * sbin[k];
        atomicMax((int*)&g_maxn[b], __float_as_int(sqrtf(s2)));
    }
}

// ---------------- dominant direction + quantize (+ folded lanczos weights) ----------------
__global__ void dom_kernel(int B) {
    int i = blockIdx.x * 256 + threadIdx.x;

    // fold: lanczos3 weight table (threads 0..511 across blocks 0,1)
    if (i < WW) {
        int o = i;
        float sf = (o + 0.5f) * 0.0625f - 0.5f;
        int i0 = (int)floorf(sf) - 2;
        float w[6];
        float tot = 0.0f;
#pragma unroll
        for (int j = 0; j < 6; j++) {
            int ii = i0 + j;
            float val = 0.0f;
            if (ii >= 0 && ii < OW) {
                float xx = fabsf(sf - (float)ii);
                float px1 = PIF * xx;
                float s1 = (xx == 0.0f) ? 1.0f : (sinf(px1) / px1);
                float x3 = xx / 3.0f;
                float px3 = PIF * x3;
                float s3 = (x3 == 0.0f) ? 1.0f : (sinf(px3) / px3);
                val = 3.0f * s1 * s3;
            }
            w[j] = val;
            tot += val;
        }
#pragma unroll
        for (int j = 0; j < 6; j++) g_wt[o * 6 + j] = w[j] / tot;
        g_ws[o] = i0;
    }

    if (i >= B * OH * OW) return;
    int b = i / (OH * OW);
    int p = i - b * (OH * OW);
    float maxn = g_maxn[b];

    float A = 0.0f, Cc = 0.0f, Bs = 0.0f;
#pragma unroll
    for (int k = 0; k < NB; k++) {
        float ck = 10.0f + 20.0f * (float)k;
        float th = (ck / 180.0f) * PIF;
        float sn = sinf(th), cs = cosf(th);
        float hn = g_hog[(b * NB + k) * (OH * OW) + p] / maxn;
        float h2 = hn * hn;
        A  += (sn * sn) * h2;
        Cc += (cs * cs) * h2;
        Bs += (sn * cs) * h2;
    }
    float Bb = -Bs;
    float half = (A - Cc) * 0.5f;
    float lam = (A + Cc) * 0.5f + sqrtf(half * half + Bb * Bb);
    float la = lam - A, lc = lam - Cc;
    float n1 = Bb * Bb + la * la;
    float n2 = lc * lc + Bb * Bb;
    bool use1 = (n1 >= n2);
    float vx = use1 ? Bb : lc;
    float vy = use1 ? la : Bb;
    float nrm = sqrtf(vx * vx + vy * vy) + 1e-9f;
    float dx = vx / nrm, dy = vy / nrm;
    g_q[(b * 2 + 0) * (OH * OW) + p] = floorf((dx + 1.0f) / 2.0f * 255.0f);
    g_q[(b * 2 + 1) * (OH * OW) + p] = floorf((dy + 1.0f) / 2.0f * 255.0f);
}

// ---------------- fused separable lanczos resize + epilogue ----------------
// block = (yt, b): 16 output rows x 512 x 2ch; 7 tmp rows in shared.
__global__ void resize_kernel(float* __restrict__ out) {
    __shared__ float stmp[2][7][WW];   // 28 KB
    int b = blockIdx.y;
    int yt = blockIdx.x;               // 0..31
    int r0 = yt - 3;                   // tmp rows r0..r0+6 (pre-clamp)
    int tid = threadIdx.x;             // 256

    const float* q0 = g_q + (b * 2 + 0) * (OH * OW);
    const float* q1 = g_q + (b * 2 + 1) * (OH * OW);

    // horizontal pass into shared: 7 rows x 512
    for (int i = tid; i < 7 * WW; i += 256) {
        int rr = i >> 9;               // 0..6
        int xo = i & 511;
        int row = min(max(r0 + rr, 0), OH - 1);
        int st = g_ws[xo];
        float s0 = 0.0f, s1 = 0.0f;
#pragma unroll
        for (int j = 0; j < 6; j++) {
            int idx = min(max(st + j, 0), OW - 1);
            float w = g_wt[xo * 6 + j];
            s0 += w * q0[row * OW + idx];
            s1 += w * q1[row * OW + idx];
        }
        stmp[0][rr][xo] = s0;
        stmp[1][rr][xo] = s1;
    }
    __syncthreads();

    // vertical pass + epilogue: 16 rows x 512
    for (int i = tid; i < 16 * WW; i += 256) {
        int ry = i >> 9;
        int x = i & 511;
        int y = yt * 16 + ry;
        int st = g_ws[y];
        float r0v = 0.0f, r1v = 0.0f;
#pragma unroll
        for (int j = 0; j < 6; j++) {
            int lr = st + j - r0;      // 0..6 by construction
            float wj = g_wt[y * 6 + j];
            r0v += wj * stmp[0][lr][x];
            r1v += wj * stmp[1][lr][x];
        }
        r0v = fminf(fmaxf(rintf(r0v), 0.0f), 255.0f);
        r1v = fminf(fmaxf(rintf(r1v), 0.0f), 255.0f);
        float o0 = (r0v / 255.0f - 0.5f) * 2.0f;
        float o1 = (r1v / 255.0f - 0.5f) * 2.0f;
        float nn = sqrtf(o0 * o0 + o1 * o1);
        out[((size_t)(b * 2 + 0) * HH + y) * WW + x] = o0 / nn;
        out[((size_t)(b * 2 + 1) * HH + y) * WW + x] = o1 / nn;
    }
}

// ---------------- launch ----------------
extern "C" void kernel_launch(void* const* d_in, const int* in_sizes, int n_in,
                              void* d_out, int out_size) {
    const float* x = (const float*)d_in[0];
    int B = in_sizes[0] / (3 * HH * WW);
    if (B > BMAX) B = BMAX;

    grad_kernel<<<dim3(WW / 32, HH / 8, B), dim3(32, 8)>>>(x);
    hog_kernel<<<dim3(OH * OW, B), 256>>>();
    int domBlocks = (B * OH * OW + 255) / 256;
    if (domBlocks < 2) domBlocks = 2;       // blocks 0,1 also build the weight table
    dom_kernel<<<domBlocks, 256>>>(B);
    resize_kernel<<<dim3(32, B), 256>>>((float*)d_out);
}

// round 8
// speedup vs baseline: 1.1289x; 1.1289x over previous
#include <cuda_runtime.h>

constexpr int HH = 512;
constexpr int WW = 512;
constexpr int NB = 9;
constexpr int OH = 32;
constexpr int OW = 32;
constexpr int BMAX = 8;

#define PIF 3.14159265358979323846f

// ---------------- scratch ----------------
__device__ float2 g_vab[BMAX * HH * WW];           // (wa*I, wb*I) per pixel
__device__ unsigned char g_k0[BMAX * HH * WW];     // base bin in [0,7]
__device__ float g_hog [BMAX * NB * OH * OW];
__device__ float g_maxn[BMAX];                     // atomicMax accumulator (>=0)
__device__ float g_tmp [BMAX * 2 * OH * WW];       // horizontally-resized rows
__device__ float g_wt  [WW * 6];
__device__ int   g_ws  [WW];

// ---------------- fused grayscale + gradient + bin decomposition (+ lanczos wt fold) ----------------
__global__ void grad_kernel(const float* __restrict__ x) {
    __shared__ float sg[10][34];
    int b = blockIdx.z;
    int x0 = blockIdx.x * 32, y0 = blockIdx.y * 8;
    const float* xb = x + (size_t)b * 3 * HH * WW;
    int tid = threadIdx.y * 32 + threadIdx.x;

    if (tid == 0) g_maxn[b] = 0.0f;   // reset for hog's atomicMax

    // fold: lanczos3 weight table, computed once by the first row of blocks of batch 0
    if (blockIdx.z == 0 && blockIdx.y == 0) {
        int o = blockIdx.x * 256 + tid;
        if (o < WW) {
            float sf = (o + 0.5f) * 0.0625f - 0.5f;
            int i0 = (int)floorf(sf) - 2;
            float w[6];
            float tot = 0.0f;
#pragma unroll
            for (int j = 0; j < 6; j++) {
                int ii = i0 + j;
                float val = 0.0f;
                if (ii >= 0 && ii < OW) {
                    float xx = fabsf(sf - (float)ii);
                    float px1 = PIF * xx;
                    float s1 = (xx == 0.0f) ? 1.0f : (sinf(px1) / px1);
                    float x3 = xx / 3.0f;
                    float px3 = PIF * x3;
                    float s3 = (x3 == 0.0f) ? 1.0f : (sinf(px3) / px3);
                    val = 3.0f * s1 * s3;
                }
                w[j] = val;
                tot += val;
            }
#pragma unroll
            for (int j = 0; j < 6; j++) g_wt[o * 6 + j] = w[j] / tot;
            g_ws[o] = i0;
        }
    }

    for (int i = tid; i < 10 * 34; i += 256) {
        int ly = i / 34, lx = i - ly * 34;
        int gy = y0 + ly - 1, gx = x0 + lx - 1;
        float v = 0.0f;
        if (gy >= 0 && gy < HH && gx >= 0 && gx < WW) {
            int p = gy * WW + gx;
            v = 0.299f * xb[p] + 0.587f * xb[p + HH * WW] + 0.114f * xb[p + 2 * HH * WW];
        }
        sg[ly][lx] = v;
    }
    __syncthreads();

    int lx = threadIdx.x, ly = threadIdx.y;
    float gx = sg[ly + 1][lx + 2] - sg[ly + 1][lx];
    float gy = sg[ly + 2][lx + 1] - sg[ly][lx + 1];
    float inten = sqrtf(gx * gx + gy * gy);
    float a = atan2f(gy, gx) + PIF;      // >= 0
    float r = fmodf(a, PIF);             // jnp.mod (positive arg) == fmod
    float o = r / PIF * 180.0f;          // [0,180)

    int k0 = (int)floorf((o - 10.0f) * 0.05f);   // [-1,8]
    float c0 = 10.0f + 20.0f * (float)k0;
    float wa = fminf(fmaxf(1.0f - (fabsf(o - c0) * 9.0f) / 180.0f, 0.0f), 1.0f);
    float wb = fminf(fmaxf(1.0f - (fabsf(o - (c0 + 20.0f)) * 9.0f) / 180.0f, 0.0f), 1.0f);
    float va = wa * inten, vb = wb * inten;
    if (k0 < 0)      { k0 = 0; va = vb; vb = 0.0f; }
    else if (k0 > 7) { k0 = 7; vb = va; va = 0.0f; }

    int p = b * HH * WW + (y0 + ly) * WW + (x0 + lx);
    g_vab[p] = make_float2(va, vb);
    g_k0[p] = (unsigned char)k0;
}

__device__ __forceinline__ int refl(int m) {
    m = (m < 0) ? -m : m;
    m = (m > HH - 1) ? (2 * (HH - 1) - m) : m;
    return m;
}

// ---------------- HOG aggregation + fused per-cell norm -> atomicMax ----------------
__global__ void hog_kernel() {
    __shared__ float sacc[NB][256];     // bank(tid) independent of bin -> conflict-free
    __shared__ int srow[33], scol[33];
    __shared__ float sbin[NB];
    int b = blockIdx.y;
    int cell = blockIdx.x;
    int oy = cell >> 5, ox = cell & 31;
    int tid = threadIdx.x;

    if (tid < 33) {
        srow[tid] = refl(oy * 16 - 16 + tid) * WW;
        scol[tid] = refl(ox * 16 - 16 + tid);
    }
#pragma unroll
    for (int k = 0; k < NB; k++) sacc[k][tid] = 0.0f;
    __syncthreads();

    const float2* __restrict__ V = g_vab + b * HH * WW;
    const unsigned char* __restrict__ K = g_k0 + b * HH * WW;

    // 1089 taps: 4 per thread + tail of 65
    float2 v[4]; float f[4]; int kk[4];
#pragma unroll
    for (int j = 0; j < 4; j++) {
        int t = tid + j * 256;
        int dy = t / 33;
        int dx = t - dy * 33;
        int gi = srow[dy] + scol[dx];
        v[j] = __ldg(&V[gi]);
        kk[j] = (int)K[gi];
        float fy = (float)(dy - 16), fx = (float)(dx - 16);
        f[j] = 1.0f - sqrtf(fy * fy + fx * fx) / 22.627417f;
    }
#pragma unroll
    for (int j = 0; j < 4; j++) {
        sacc[kk[j]][tid]     += f[j] * v[j].x;
        sacc[kk[j] + 1][tid] += f[j] * v[j].y;
    }
    if (tid < 65) {
        int t = 1024 + tid;
        int dy = t / 33;
        int dx = t - dy * 33;
        int gi = srow[dy] + scol[dx];
        float2 vt = __ldg(&V[gi]);
        int kt = (int)K[gi];
        float fy = (float)(dy - 16), fx = (float)(dx - 16);
        float ft = 1.0f - sqrtf(fy * fy + fx * fx) / 22.627417f;
        sacc[kt][tid]     += ft * vt.x;
        sacc[kt + 1][tid] += ft * vt.y;
    }
    __syncthreads();

    // warp w reduces bins k = w, w+8 (strided LDS + shuffle tree)
    int w = tid >> 5, l = tid & 31;
    for (int k = w; k < NB; k += 8) {
        float s = 0.0f;
#pragma unroll
        for (int i = 0; i < 8; i++) s += sacc[k][l + 32 * i];
#pragma unroll
        for (int off = 16; off > 0; off >>= 1)
            s += __shfl_down_sync(0xffffffffu, s, off);
        if (l == 0) {
            g_hog[(b * NB + k) * (OH * OW) + cell] = s;
            sbin[k] = s;
        }
    }
    __syncthreads();

    // cell L2 norm over bins -> per-batch max (atomic on int view; all values >= 0)
    if (tid == 0) {
        float s2 = 0.0f;
#pragma unroll
        for (int k = 0; k < NB; k++) s2 += sbin[k] * sbin[k];
        atomicMax((int*)&g_maxn[b], __float_as_int(sqrtf(s2)));
    }
}

// ---------------- fused dominant-direction + quantize + horizontal lanczos pass ----------------
// block = (row, b): dom for 32 cells of this row (threads 0-31), then hpass 2ch x 512.
__global__ void domh_kernel() {
    __shared__ float qs[2][OW];
    int b = blockIdx.y;
    int row = blockIdx.x;              // 0..31
    int tid = threadIdx.x;             // 256

    if (tid < OW) {
        int p = row * OW + tid;
        float maxn = g_maxn[b];
        float A = 0.0f, Cc = 0.0f, Bs = 0.0f;
#pragma unroll
        for (int k = 0; k < NB; k++) {
            float ck = 10.0f + 20.0f * (float)k;
            float th = (ck / 180.0f) * PIF;
            float sn = sinf(th), cs = cosf(th);
            float hn = g_hog[(b * NB + k) * (OH * OW) + p] / maxn;
            float h2 = hn * hn;
            A  += (sn * sn) * h2;
            Cc += (cs * cs) * h2;
            Bs += (sn * cs) * h2;
        }
        float Bb = -Bs;
        float half = (A - Cc) * 0.5f;
        float lam = (A + Cc) * 0.5f + sqrtf(half * half + Bb * Bb);
        float la = lam - A, lc = lam - Cc;
        float n1 = Bb * Bb + la * la;
        float n2 = lc * lc + Bb * Bb;
        bool use1 = (n1 >= n2);
        float vx = use1 ? Bb : lc;
        float vy = use1 ? la : Bb;
        float nrm = sqrtf(vx * vx + vy * vy) + 1e-9f;
        qs[0][tid] = floorf((vx / nrm + 1.0f) / 2.0f * 255.0f);
        qs[1][tid] = floorf((vy / nrm + 1.0f) / 2.0f * 255.0f);
    }
    __syncthreads();

    // horizontal pass: 2 channels x 512 outputs
    for (int i = tid; i < 2 * WW; i += 256) {
        int c = i >> 9;
        int xo = i & 511;
        int st = g_ws[xo];
        float s = 0.0f;
#pragma unroll
        for (int j = 0; j < 6; j++) {
            int idx = min(max(st + j, 0), OW - 1);
            s += g_wt[xo * 6 + j] * qs[c][idx];
        }
        g_tmp[(b * 2 + c) * (OH * WW) + row * WW + xo] = s;
    }
}

// ---------------- vertical pass + round/clip + normalize ----------------
__global__ void vpass_kernel(float* __restrict__ out, int B) {
    int i = blockIdx.x * blockDim.x + threadIdx.x;
    int n = B * HH * WW;
    if (i >= n) return;
    int x = i % WW;
    int y = (i / WW) % HH;
    int b = i / (HH * WW);
    int st = g_ws[y];
    const float* t0 = g_tmp + (b * 2 + 0) * (OH * WW);
    const float* t1 = g_tmp + (b * 2 + 1) * (OH * WW);
    float r0 = 0.0f, r1 = 0.0f;
#pragma unroll
    for (int j = 0; j < 6; j++) {
        int idx = min(max(st + j, 0), OH - 1);
        float wj = g_wt[y * 6 + j];
        r0 += wj * t0[idx * WW + x];
        r1 += wj * t1[idx * WW + x];
    }
    r0 = fminf(fmaxf(rintf(r0), 0.0f), 255.0f);
    r1 = fminf(fmaxf(rintf(r1), 0.0f), 255.0f);
    float o0 = (r0 / 255.0f - 0.5f) * 2.0f;
    float o1 = (r1 / 255.0f - 0.5f) * 2.0f;
    float nn = sqrtf(o0 * o0 + o1 * o1);
    out[((size_t)(b * 2 + 0) * HH + y) * WW + x] = o0 / nn;
    out[((size_t)(b * 2 + 1) * HH + y) * WW + x] = o1 / nn;
}

// ---------------- launch ----------------
extern "C" void kernel_launch(void* const* d_in, const int* in_sizes, int n_in,
                              void* d_out, int out_size) {
    const float* x = (const float*)d_in[0];
    int B = in_sizes[0] / (3 * HH * WW);
    if (B > BMAX) B = BMAX;
    int npix = B * HH * WW;

    grad_kernel<<<dim3(WW / 32, HH / 8, B), dim3(32, 8)>>>(x);
    hog_kernel<<<dim3(OH * OW, B), 256>>>();
    domh_kernel<<<dim3(OH, B), 256>>>();
    vpass_kernel<<<(npix + 255) / 256, 256>>>((float*)d_out, B);
}

// round 9
// speedup vs baseline: 1.1604x; 1.0279x over previous
#include <cuda_runtime.h>

constexpr int HH = 512;
constexpr int WW = 512;
constexpr int NB = 9;
constexpr int OH = 32;
constexpr int OW = 32;
constexpr int BMAX = 8;

#define PIF 3.14159265358979323846f

// ---------------- scratch ----------------
__device__ float2 g_vab[BMAX * HH * WW];           // (wa*I, wb*I) per pixel
__device__ unsigned char g_k0[BMAX * HH * WW];     // base bin in [0,7]
__device__ float g_hog [BMAX * NB * OH * OW];
__device__ float g_maxn[BMAX];                     // atomicMax accumulator (>=0)
__device__ float g_tmp [BMAX * 2 * OH * WW];       // horizontally-resized rows
__device__ float g_wt  [WW * 6];
__device__ int   g_ws  [WW];

// ---------------- fused grayscale + gradient + bin decomposition (+ lanczos wt fold) ----------------
__global__ void grad_kernel(const float* __restrict__ x) {
    __shared__ float sg[10][34];
    int b = blockIdx.z;
    int x0 = blockIdx.x * 32, y0 = blockIdx.y * 8;
    const float* xb = x + (size_t)b * 3 * HH * WW;
    int tid = threadIdx.y * 32 + threadIdx.x;

    if (tid == 0) g_maxn[b] = 0.0f;   // reset for hog's atomicMax

    // fold: lanczos3 weight table, computed once by the first row of blocks of batch 0
    if (blockIdx.z == 0 && blockIdx.y == 0) {
        int o = blockIdx.x * 256 + tid;
        if (o < WW) {
            float sf = (o + 0.5f) * 0.0625f - 0.5f;
            int i0 = (int)floorf(sf) - 2;
            float w[6];
            float tot = 0.0f;
#pragma unroll
            for (int j = 0; j < 6; j++) {
                int ii = i0 + j;
                float val = 0.0f;
                if (ii >= 0 && ii < OW) {
                    float xx = fabsf(sf - (float)ii);
                    float px1 = PIF * xx;
                    float s1 = (xx == 0.0f) ? 1.0f : (sinf(px1) / px1);
                    float x3 = xx / 3.0f;
                    float px3 = PIF * x3;
                    float s3 = (x3 == 0.0f) ? 1.0f : (sinf(px3) / px3);
                    val = 3.0f * s1 * s3;
                }
                w[j] = val;
                tot += val;
            }
#pragma unroll
            for (int j = 0; j < 6; j++) g_wt[o * 6 + j] = w[j] / tot;
            g_ws[o] = i0;
        }
    }

    for (int i = tid; i < 10 * 34; i += 256) {
        int ly = i / 34, lx = i - ly * 34;
        int gy = y0 + ly - 1, gx = x0 + lx - 1;
        float v = 0.0f;
        if (gy >= 0 && gy < HH && gx >= 0 && gx < WW) {
            int p = gy * WW + gx;
            v = 0.299f * xb[p] + 0.587f * xb[p + HH * WW] + 0.114f * xb[p + 2 * HH * WW];
        }
        sg[ly][lx] = v;
    }
    __syncthreads();

    int lx = threadIdx.x, ly = threadIdx.y;
    float gx = sg[ly + 1][lx + 2] - sg[ly + 1][lx];
    float gy = sg[ly + 2][lx + 1] - sg[ly][lx + 1];
    float inten = sqrtf(gx * gx + gy * gy);
    float a = atan2f(gy, gx) + PIF;      // >= 0
    float r = fmodf(a, PIF);             // jnp.mod (positive arg) == fmod
    float o = r / PIF * 180.0f;          // [0,180)

    int k0 = (int)floorf((o - 10.0f) * 0.05f);   // [-1,8]
    float c0 = 10.0f + 20.0f * (float)k0;
    float wa = fminf(fmaxf(1.0f - (fabsf(o - c0) * 9.0f) / 180.0f, 0.0f), 1.0f);
    float wb = fminf(fmaxf(1.0f - (fabsf(o - (c0 + 20.0f)) * 9.0f) / 180.0f, 0.0f), 1.0f);
    float va = wa * inten, vb = wb * inten;
    if (k0 < 0)      { k0 = 0; va = vb; vb = 0.0f; }
    else if (k0 > 7) { k0 = 7; vb = va; va = 0.0f; }

    int p = b * HH * WW + (y0 + ly) * WW + (x0 + lx);
    g_vab[p] = make_float2(va, vb);
    g_k0[p] = (unsigned char)k0;
}

__device__ __forceinline__ int refl(int m) {
    m = (m < 0) ? -m : m;
    m = (m > HH - 1) ? (2 * (HH - 1) - m) : m;
    return m;
}

// ---------------- HOG aggregation + fused per-cell norm -> atomicMax ----------------
__global__ void hog_kernel() {
    __shared__ float sacc[NB][256];     // bank(tid) independent of bin -> conflict-free
    __shared__ int srow[33], scol[33];
    __shared__ float sbin[NB];
    int b = blockIdx.y;
    int cell = blockIdx.x;
    int oy = cell >> 5, ox = cell & 31;
    int tid = threadIdx.x;

    if (tid < 33) {
        srow[tid] = refl(oy * 16 - 16 + tid) * WW;
        scol[tid] = refl(ox * 16 - 16 + tid);
    }
#pragma unroll
    for (int k = 0; k < NB; k++) sacc[k][tid] = 0.0f;
    __syncthreads();

    const float2* __restrict__ V = g_vab + b * HH * WW;
    const unsigned char* __restrict__ K = g_k0 + b * HH * WW;

    // 1089 taps: 4 per thread + tail of 65
    float2 v[4]; float f[4]; int kk[4];
#pragma unroll
    for (int j = 0; j < 4; j++) {
        int t = tid + j * 256;
        int dy = t / 33;
        int dx = t - dy * 33;
        int gi = srow[dy] + scol[dx];
        v[j] = __ldg(&V[gi]);
        kk[j] = (int)K[gi];
        float fy = (float)(dy - 16), fx = (float)(dx - 16);
        f[j] = 1.0f - sqrtf(fy * fy + fx * fx) / 22.627417f;
    }
#pragma unroll
    for (int j = 0; j < 4; j++) {
        sacc[kk[j]][tid]     += f[j] * v[j].x;
        sacc[kk[j] + 1][tid] += f[j] * v[j].y;
    }
    if (tid < 65) {
        int t = 1024 + tid;
        int dy = t / 33;
        int dx = t - dy * 33;
        int gi = srow[dy] + scol[dx];
        float2 vt = __ldg(&V[gi]);
        int kt = (int)K[gi];
        float fy = (float)(dy - 16), fx = (float)(dx - 16);
        float ft = 1.0f - sqrtf(fy * fy + fx * fx) / 22.627417f;
        sacc[kt][tid]     += ft * vt.x;
        sacc[kt + 1][tid] += ft * vt.y;
    }
    __syncthreads();

    // warp w reduces bins k = w, w+8 (strided LDS + shuffle tree)
    int w = tid >> 5, l = tid & 31;
    for (int k = w; k < NB; k += 8) {
        float s = 0.0f;
#pragma unroll
        for (int i = 0; i < 8; i++) s += sacc[k][l + 32 * i];
#pragma unroll
        for (int off = 16; off > 0; off >>= 1)
            s += __shfl_down_sync(0xffffffffu, s, off);
        if (l == 0) {
            g_hog[(b * NB + k) * (OH * OW) + cell] = s;
            sbin[k] = s;
        }
    }
    __syncthreads();

    // cell L2 norm over bins -> per-batch max (atomic on int view; all values >= 0)
    if (tid == 0) {
        float s2 = 0.0f;
#pragma unroll
        for (int k = 0; k < NB; k++) s2 += sbin[k] * sbin[k];
        atomicMax((int*)&g_maxn[b], __float_as_int(sqrtf(s2)));
    }
}

// ---------------- fused dominant-direction + quantize + horizontal lanczos pass ----------------
// block = (row, b): dom for 32 cells of this row (threads 0-31), then hpass 2ch x 512.
__global__ void domh_kernel() {
    __shared__ float qs[2][OW];
    int b = blockIdx.y;
    int row = blockIdx.x;              // 0..31
    int tid = threadIdx.x;             // 256

    if (tid < OW) {
        int p = row * OW + tid;
        float maxn = g_maxn[b];
        float A = 0.0f, Cc = 0.0f, Bs = 0.0f;
#pragma unroll
        for (int k = 0; k < NB; k++) {
            float ck = 10.0f + 20.0f * (float)k;
            float th = (ck / 180.0f) * PIF;
            float sn = sinf(th), cs = cosf(th);
            float hn = g_hog[(b * NB + k) * (OH * OW) + p] / maxn;
            float h2 = hn * hn;
            A  += (sn * sn) * h2;
            Cc += (cs * cs) * h2;
            Bs += (sn * cs) * h2;
        }
        float Bb = -Bs;
        float half = (A - Cc) * 0.5f;
        float lam = (A + Cc) * 0.5f + sqrtf(half * half + Bb * Bb);
        float la = lam - A, lc = lam - Cc;
        float n1 = Bb * Bb + la * la;
        float n2 = lc * lc + Bb * Bb;
        bool use1 = (n1 >= n2);
        float vx = use1 ? Bb : lc;
        float vy = use1 ? la : Bb;
        float nrm = sqrtf(vx * vx + vy * vy) + 1e-9f;
        qs[0][tid] = floorf((vx / nrm + 1.0f) / 2.0f * 255.0f);
        qs[1][tid] = floorf((vy / nrm + 1.0f) / 2.0f * 255.0f);
    }
    __syncthreads();

    // horizontal pass: 2 channels x 512 outputs
    for (int i = tid; i < 2 * WW; i += 256) {
        int c = i >> 9;
        int xo = i & 511;
        int st = g_ws[xo];
        float s = 0.0f;
#pragma unroll
        for (int j = 0; j < 6; j++) {
            int idx = min(max(st + j, 0), OW - 1);
            s += g_wt[xo * 6 + j] * qs[c][idx];
        }
        g_tmp[(b * 2 + c) * (OH * WW) + row * WW + xo] = s;
    }
}

// ---------------- vertical pass + epilogue: one block per output row, float4 ----------------
__global__ void vpass_kernel(float* __restrict__ out, int B) {
    int rowid = blockIdx.x;            // b * HH + y
    int b = rowid >> 9;
    int y = rowid & 511;
    int x4 = threadIdx.x * 4;          // 128 threads x 4 pixels

    // block-uniform: tap rows + weights
    int st = __ldg(&g_ws[y]);
    float w[6];
    int ro[6];
#pragma unroll
    for (int j = 0; j < 6; j++) {
        w[j] = __ldg(&g_wt[y * 6 + j]);
        ro[j] = min(max(st + j, 0), OH - 1) * WW;
    }

    const float* t0 = g_tmp + (b * 2 + 0) * (OH * WW);
    const float* t1 = g_tmp + (b * 2 + 1) * (OH * WW);

    float4 r0 = make_float4(0.f, 0.f, 0.f, 0.f);
    float4 r1 = make_float4(0.f, 0.f, 0.f, 0.f);
#pragma unroll
    for (int j = 0; j < 6; j++) {
        float4 a = __ldg((const float4*)(t0 + ro[j] + x4));
        float4 c = __ldg((const float4*)(t1 + ro[j] + x4));
        r0.x += w[j] * a.x; r0.y += w[j] * a.y; r0.z += w[j] * a.z; r0.w += w[j] * a.w;
        r1.x += w[j] * c.x; r1.y += w[j] * c.y; r1.z += w[j] * c.z; r1.w += w[j] * c.w;
    }

    float4 o0, o1;
    {
        float* pr0 = &r0.x; float* pr1 = &r1.x;
        float* po0 = &o0.x; float* po1 = &o1.x;
#pragma unroll
        for (int q = 0; q < 4; q++) {
            float a = fminf(fmaxf(rintf(pr0[q]), 0.0f), 255.0f);
            float c = fminf(fmaxf(rintf(pr1[q]), 0.0f), 255.0f);
            float u = (a / 255.0f - 0.5f) * 2.0f;
            float v = (c / 255.0f - 0.5f) * 2.0f;
            float nn = sqrtf(u * u + v * v);
            po0[q] = u / nn;
            po1[q] = v / nn;
        }
    }
    *(float4*)(out + ((size_t)(b * 2 + 0) * HH + y) * WW + x4) = o0;
    *(float4*)(out + ((size_t)(b * 2 + 1) * HH + y) * WW + x4) = o1;
}

// ---------------- launch ----------------
extern "C" void kernel_launch(void* const* d_in, const int* in_sizes, int n_in,
                              void* d_out, int out_size) {
    const float* x = (const float*)d_in[0];
    int B = in_sizes[0] / (3 * HH * WW);
    if (B > BMAX) B = BMAX;

    grad_kernel<<<dim3(WW / 32, HH / 8, B), dim3(32, 8)>>>(x);
    hog_kernel<<<dim3(OH * OW, B), 256>>>();
    domh_kernel<<<dim3(OH, B), 256>>>();
    vpass_kernel<<<B * HH, 128>>>((float*)d_out, B);
}